// round 9
// baseline (speedup 1.0000x reference)
#include <cuda_runtime.h>
#include <cuda_bf16.h>

#define NT 48
#define SEQ 512
#define BATCH 1024
#define BPB 2                 // batches per work unit (pair)
#define THREADS (BPB * NT)    // 96 threads = 3 warps
#define NPAIRS (BATCH / BPB)  // 512 work units
#define NBLOCKS 456           // 152 SMs * 3 resident blocks (GB300)

__device__ int g_ctr;

__global__ void reset_ctr_kernel() { g_ctr = 0; }

// Persistent Viterbi forward: blocks pop batch-pairs from a global queue.
// Per pair: one thread per (batch, tag_j), T[:,j] column in registers
// (loaded ONCE per block, reused across pairs), state in SMEM double buffer,
// one barrier per step, fused (value, float-index) max tree (bit-exact argmax).
__global__ __launch_bounds__(THREADS, 3)
void crf_viterbi_kernel(const float* __restrict__ pot,
                        const float* __restrict__ trans,
                        float* __restrict__ out)
{
    __shared__ __align__(16) float st[2][BPB][NT];
    __shared__ int s_pair;

    const int tid = threadIdx.x;
    const int lb  = tid / NT;
    const int j   = tid - lb * NT;

    // Transition column T[i][j] in registers — pair-independent, loaded once.
    float tc[NT];
#pragma unroll
    for (int i = 0; i < NT; i++) tc[i] = trans[i * NT + j];

    float* const scores = out + (size_t)BATCH * (SEQ - 1) * NT;

    while (true) {
        if (tid == 0) s_pair = atomicAdd(&g_ctr, 1);
        __syncthreads();
        const int pair = s_pair;
        if (pair >= NPAIRS) break;

        const int b = pair * BPB + lb;
        const float* potb = pot + (size_t)b * SEQ * NT + j;
        float* bpp        = out + (size_t)b * (SEQ - 1) * NT + j;

        float ns = potb[0];
        st[0][lb][j] = ns;
        __syncthreads();

        // 2-deep prefetch of unary potentials, running pointer
        const float* pp = potb + 3 * NT;
        float pn1 = potb[NT];
        float pn2 = potb[2 * NT];
        int buf = 0;

#pragma unroll 2
        for (int t = 1; t < SEQ; ++t) {
            const float p = pn1;
            pn1 = pn2;
            if (t + 2 < SEQ) { pn2 = *pp; pp += NT; }

            // Load state (12x LDS.128, broadcast within batch group) and add tc
            float s[NT];
            const float4* sp = (const float4*)st[buf][lb];
#pragma unroll
            for (int k = 0; k < NT / 4; k++) {
                float4 q = sp[k];
                s[4 * k + 0] = q.x + tc[4 * k + 0];
                s[4 * k + 1] = q.y + tc[4 * k + 1];
                s[4 * k + 2] = q.z + tc[4 * k + 2];
                s[4 * k + 3] = q.w + tc[4 * k + 3];
            }

            // Fused (value, float-index) tree. 48 -> 24 -> 12 -> 6 -> 3 -> 1.
            // Strict r>l per node, left carries lower index => exact
            // first-occurrence argmax (jnp semantics), bit-exact values.
            float v1[24], i1[24];
#pragma unroll
            for (int k = 0; k < 24; k++) {
                const bool pr = (s[2 * k + 1] > s[2 * k]);
                v1[k] = fmaxf(s[2 * k], s[2 * k + 1]);
                i1[k] = pr ? (float)(2 * k + 1) : (float)(2 * k);
            }
            float v2[12], i2[12];
#pragma unroll
            for (int k = 0; k < 12; k++) {
                const bool pr = (v1[2 * k + 1] > v1[2 * k]);
                v2[k] = fmaxf(v1[2 * k], v1[2 * k + 1]);
                i2[k] = pr ? i1[2 * k + 1] : i1[2 * k];
            }
            float v3[6], i3[6];
#pragma unroll
            for (int k = 0; k < 6; k++) {
                const bool pr = (v2[2 * k + 1] > v2[2 * k]);
                v3[k] = fmaxf(v2[2 * k], v2[2 * k + 1]);
                i3[k] = pr ? i2[2 * k + 1] : i2[2 * k];
            }
            float v4[3], i4[3];
#pragma unroll
            for (int k = 0; k < 3; k++) {
                const bool pr = (v3[2 * k + 1] > v3[2 * k]);
                v4[k] = fmaxf(v3[2 * k], v3[2 * k + 1]);
                i4[k] = pr ? i3[2 * k + 1] : i3[2 * k];
            }
            const bool p01 = (v4[1] > v4[0]);
            const float mv01 = fmaxf(v4[0], v4[1]);
            const float mi01 = p01 ? i4[1] : i4[0];
            const bool p2  = (v4[2] > mv01);
            const float m    = fmaxf(mv01, v4[2]);
            const float fidx = p2 ? i4[2] : mi01;

            ns = p + m;                        // bit-exact vs reference
            st[buf ^ 1][lb][j] = ns;
            bpp[0] = fidx;
            bpp += NT;
            __syncthreads();
            buf ^= 1;
        }

        scores[(size_t)b * NT + j] = ns;
        __syncthreads();   // all reads of st/s_pair done before next pop
    }
}

extern "C" void kernel_launch(void* const* d_in, const int* in_sizes, int n_in,
                              void* d_out, int out_size)
{
    const float* pot   = (const float*)d_in[0];
    const float* trans = (const float*)d_in[1];
    float* out         = (float*)d_out;
    reset_ctr_kernel<<<1, 1>>>();
    crf_viterbi_kernel<<<NBLOCKS, THREADS>>>(pot, trans, out);
}

// round 10
// speedup vs baseline: 1.7195x; 1.7195x over previous
#include <cuda_runtime.h>
#include <cuda_bf16.h>

#define NT 48
#define SEQ 512
#define BATCH 1024
#define BPB 2                 // batches per block
#define THREADS (BPB * NT)    // 96 threads = 3 warps

// Viterbi forward: one thread per (batch, tag_j).
//   - T[:, j] column in 48 registers
//   - state in SMEM, double buffered, one barrier per step
//   - fused (value, float-index) balanced tree (3 ops/node, exact argmax)
//   - backpointer STG issued AFTER the barrier (off the arrival path)
//   - branch-free clamped potential prefetch
__global__ __launch_bounds__(THREADS, 4)
void crf_viterbi_kernel(const float* __restrict__ pot,
                        const float* __restrict__ trans,
                        float* __restrict__ out)
{
    __shared__ __align__(16) float st[2][BPB][NT];

    const int tid = threadIdx.x;
    const int lb  = tid / NT;
    const int j   = tid - lb * NT;
    const int b   = blockIdx.x * BPB + lb;

    // Transition column T[i][j] in registers
    float tc[NT];
#pragma unroll
    for (int i = 0; i < NT; i++) tc[i] = trans[i * NT + j];

    const float* potb = pot + (size_t)b * SEQ * NT + j;
    float* bpp        = out + (size_t)b * (SEQ - 1) * NT + j;
    float* scores     = out + (size_t)BATCH * (SEQ - 1) * NT;

    float ns = potb[0];
    st[0][lb][j] = ns;
    __syncthreads();

    // 2-deep prefetch, branch-free: offset clamps at the last row
    int off = 3 * NT;
    const int offmax = (SEQ - 1) * NT;
    float pn1 = potb[NT];
    float pn2 = potb[2 * NT];
    int buf = 0;

#pragma unroll 2
    for (int t = 1; t < SEQ; ++t) {
        const float p = pn1;
        pn1 = pn2;
        pn2 = potb[off];                      // clamped, unconditional
        off = min(off + NT, offmax);

        // Load state (12x LDS.128, broadcast within batch group) and add tc
        float s[NT];
        const float4* sp = (const float4*)st[buf][lb];
#pragma unroll
        for (int k = 0; k < NT / 4; k++) {
            float4 q = sp[k];
            s[4 * k + 0] = q.x + tc[4 * k + 0];
            s[4 * k + 1] = q.y + tc[4 * k + 1];
            s[4 * k + 2] = q.z + tc[4 * k + 2];
            s[4 * k + 3] = q.w + tc[4 * k + 3];
        }

        // Fused (value, float-index) tree. 48 -> 24 -> 12 -> 6 -> 3 -> 1.
        // Strict r>l per node, left carries lower index => exact
        // first-occurrence argmax (jnp semantics), bit-exact values.
        float v1[24], i1[24];
#pragma unroll
        for (int k = 0; k < 24; k++) {
            const bool pr = (s[2 * k + 1] > s[2 * k]);
            v1[k] = fmaxf(s[2 * k], s[2 * k + 1]);
            i1[k] = pr ? (float)(2 * k + 1) : (float)(2 * k);
        }
        float v2[12], i2[12];
#pragma unroll
        for (int k = 0; k < 12; k++) {
            const bool pr = (v1[2 * k + 1] > v1[2 * k]);
            v2[k] = fmaxf(v1[2 * k], v1[2 * k + 1]);
            i2[k] = pr ? i1[2 * k + 1] : i1[2 * k];
        }
        float v3[6], i3[6];
#pragma unroll
        for (int k = 0; k < 6; k++) {
            const bool pr = (v2[2 * k + 1] > v2[2 * k]);
            v3[k] = fmaxf(v2[2 * k], v2[2 * k + 1]);
            i3[k] = pr ? i2[2 * k + 1] : i2[2 * k];
        }
        float v4[3], i4[3];
#pragma unroll
        for (int k = 0; k < 3; k++) {
            const bool pr = (v3[2 * k + 1] > v3[2 * k]);
            v4[k] = fmaxf(v3[2 * k], v3[2 * k + 1]);
            i4[k] = pr ? i3[2 * k + 1] : i3[2 * k];
        }
        const bool p01 = (v4[1] > v4[0]);
        const float mv01 = fmaxf(v4[0], v4[1]);
        const float mi01 = p01 ? i4[1] : i4[0];
        const bool p2  = (v4[2] > mv01);
        const float m    = fmaxf(mv01, v4[2]);
        const float fidx = p2 ? i4[2] : mi01;

        ns = p + m;                        // bit-exact vs reference
        st[buf ^ 1][lb][j] = ns;           // publish state, then barrier
        __syncthreads();
        bpp[0] = fidx;                     // STG off the arrival path
        bpp += NT;
        buf ^= 1;
    }

    scores[(size_t)b * NT + j] = ns;
}

extern "C" void kernel_launch(void* const* d_in, const int* in_sizes, int n_in,
                              void* d_out, int out_size)
{
    const float* pot   = (const float*)d_in[0];
    const float* trans = (const float*)d_in[1];
    float* out         = (float*)d_out;
    crf_viterbi_kernel<<<BATCH / BPB, THREADS>>>(pot, trans, out);
}